// round 4
// baseline (speedup 1.0000x reference)
#include <cuda_runtime.h>
#include <math.h>

#define H   128
#define H2  256
#define H3  384
#define WMC 257          // W_msg columns = 2H+1

#define MAXN 50000
#define MAXE 800000
#define MAXT 4

// ---------------- scratch (static device globals; no allocation) ----------------
__device__ float g_X  [(size_t)MAXN * H2];   // [deg*hv, S]
__device__ float g_gi [(size_t)MAXN * H3];
__device__ float g_gh [(size_t)MAXN * H3];
__device__ float g_h0 [(size_t)MAXN * H];
__device__ float g_h1 [(size_t)MAXN * H];
__device__ float g_deg[MAXN];
__device__ float g_se [MAXN];
__device__ float g_Wc [(size_t)MAXT * H3 * H2];  // W_ih @ W_msg[:, :2H]
__device__ float g_u1 [MAXT * H3];               // W_ih @ w_e
__device__ float g_u2 [MAXT * H3];               // W_ih @ b_msg
__device__ int   g_off [MAXN + 1];               // CSR offsets (by dst)
__device__ int   g_cur [MAXN];                   // fill cursors
__device__ int   g_csrc[MAXE];                   // CSR src lists

// ---------------- utility ----------------
__global__ void zero_kernel(float* __restrict__ p, size_t n) {
    size_t i = (size_t)blockIdx.x * blockDim.x + threadIdx.x;
    size_t stride = (size_t)gridDim.x * blockDim.x;
    for (; i < n; i += stride) p[i] = 0.f;
}

// ---------------- per-graph aggregates (round-invariant) ----------------
__global__ void degse_kernel(const int* __restrict__ dst, const float* __restrict__ he, int E) {
    int e = blockIdx.x * blockDim.x + threadIdx.x;
    if (e >= E) return;
    int d = dst[e];
    atomicAdd(&g_deg[d], 1.0f);
    atomicAdd(&g_se[d], he[e]);
}

// ---------------- CSR build: exclusive prefix scan of deg (single block) ----------
__global__ void scan_kernel(int N) {
    __shared__ int sh[1024];
    __shared__ int carry;
    int tid = threadIdx.x;
    if (tid == 0) carry = 0;
    __syncthreads();
    for (int base = 0; base < N; base += 1024) {
        int v = (base + tid < N) ? (int)g_deg[base + tid] : 0;
        sh[tid] = v;
        __syncthreads();
        #pragma unroll
        for (int off = 1; off < 1024; off <<= 1) {
            int t = (tid >= off) ? sh[tid - off] : 0;
            __syncthreads();
            sh[tid] += t;
            __syncthreads();
        }
        if (base + tid < N) {
            int ex = carry + sh[tid] - v;
            g_off[base + tid] = ex;
            g_cur[base + tid] = ex;
        }
        int total = sh[1023];
        __syncthreads();
        if (tid == 0) carry += total;
        __syncthreads();
    }
    if (tid == 0) g_off[N] = carry;
}

__global__ void fill_kernel(const int* __restrict__ src, const int* __restrict__ dst, int E) {
    int e = blockIdx.x * blockDim.x + threadIdx.x;
    if (e >= E) return;
    int pos = atomicAdd(&g_cur[dst[e]], 1);
    g_csrc[pos] = src[e];
}

// ---------------- weight folding ----------------
__global__ void fold_wc_kernel(const float* __restrict__ W_ih, const float* __restrict__ W_msg, int T) {
    long idx = (long)blockIdx.x * blockDim.x + threadIdx.x;
    if (idx >= (long)T * H3 * H2) return;
    int k = (int)(idx % H2);
    int j = (int)((idx / H2) % H3);
    int t = (int)(idx / ((long)H2 * H3));
    const float* wi = W_ih + ((size_t)t * H3 + j) * H2;
    const float* wm = W_msg + (size_t)t * H2 * WMC + k;
    float a0 = 0.f, a1 = 0.f, a2 = 0.f, a3 = 0.f;
    #pragma unroll 2
    for (int i = 0; i < H2; i += 4) {
        a0 += __ldg(wi + i)     * __ldg(wm + (size_t)(i)     * WMC);
        a1 += __ldg(wi + i + 1) * __ldg(wm + (size_t)(i + 1) * WMC);
        a2 += __ldg(wi + i + 2) * __ldg(wm + (size_t)(i + 2) * WMC);
        a3 += __ldg(wi + i + 3) * __ldg(wm + (size_t)(i + 3) * WMC);
    }
    g_Wc[idx] = (a0 + a1) + (a2 + a3);
}

__global__ void fold_u_kernel(const float* __restrict__ W_ih, const float* __restrict__ W_msg,
                              const float* __restrict__ b_msg, int T) {
    int idx = blockIdx.x * blockDim.x + threadIdx.x;
    if (idx >= T * H3) return;
    int j = idx % H3, t = idx / H3;
    const float* wi = W_ih + ((size_t)t * H3 + j) * H2;
    const float* wm = W_msg + (size_t)t * H2 * WMC;
    const float* bm = b_msg + (size_t)t * H2;
    float a1 = 0.f, a2 = 0.f;
    for (int i = 0; i < H2; i++) {
        float w = wi[i];
        a1 += w * wm[(size_t)i * WMC + H2];
        a2 += w * bm[i];
    }
    g_u1[idx] = a1;
    g_u2[idx] = a2;
}

// ---------------- gather + X build: one warp per node ----------------
// X[n] = [deg*hv[n], sum_{e in CSR[n]} hv[csrc[e]]]
__global__ void gatherx_kernel(const float* __restrict__ hv, int N) {
    int n = (blockIdx.x * blockDim.x + threadIdx.x) >> 5;
    int lane = threadIdx.x & 31;
    if (n >= N) return;
    int beg = g_off[n], end = g_off[n + 1];
    float4 acc = make_float4(0.f, 0.f, 0.f, 0.f);
    for (int e = beg; e < end; e++) {
        int s = __ldg(g_csrc + e);
        float4 v = *(((const float4*)(hv + (size_t)s * H)) + lane);
        acc.x += v.x; acc.y += v.y; acc.z += v.z; acc.w += v.w;
    }
    float dg = (float)(end - beg);
    float4 hvv = *(((const float4*)(hv + (size_t)n * H)) + lane);
    hvv.x *= dg; hvv.y *= dg; hvv.z *= dg; hvv.w *= dg;
    float4* xp = (float4*)(g_X + (size_t)n * H2);
    xp[lane] = hvv;
    xp[lane + 32] = acc;
}

// ---------------- 3xTF32 tensor-core GEMM (NT): C = A @ B^T, fp32-accurate ---------
// 128x128 block tile, BK=16, 256 threads (8 warps, 2x4), warp tile 64x32.
// Register-prefetch pipeline: next tile's global loads issue before the mma block.
#define SMS 136

__device__ __forceinline__ unsigned f2tf32(float f) {
    unsigned r;
    asm("cvt.rna.tf32.f32 %0, %1;" : "=r"(r) : "f"(f));
    return r;
}

__device__ __forceinline__ void split_tf32(float f, unsigned& hi, unsigned& lo) {
    hi = f2tf32(f);
    float r = f - __uint_as_float(hi);
    lo = f2tf32(r);
}

__device__ __forceinline__ void mma_tf32(float* acc, const unsigned* a, const unsigned* b) {
    asm volatile(
        "mma.sync.aligned.m16n8k8.row.col.f32.tf32.tf32.f32 "
        "{%0,%1,%2,%3}, {%4,%5,%6,%7}, {%8,%9}, {%0,%1,%2,%3};"
        : "+f"(acc[0]), "+f"(acc[1]), "+f"(acc[2]), "+f"(acc[3])
        : "r"(a[0]), "r"(a[1]), "r"(a[2]), "r"(a[3]), "r"(b[0]), "r"(b[1]));
}

__global__ __launch_bounds__(256) void mma_tf32x3_nt(
    const float* __restrict__ A, const float* __restrict__ B, float* __restrict__ C,
    int M, int Nout, int K)
{
    __shared__ unsigned AsH[16 * SMS];
    __shared__ unsigned AsL[16 * SMS];
    __shared__ unsigned BsH[16 * SMS];
    __shared__ unsigned BsL[16 * SMS];

    int bm = blockIdx.x, bn = blockIdx.y;
    int tid = threadIdx.x;
    int lane = tid & 31;
    int warp = tid >> 5;
    int wm = warp >> 2;        // 0..1
    int wn = warp & 3;         // 0..3
    int mb = wm * 64;
    int nb = wn * 32;
    int qk = lane & 3;
    int qm = lane >> 2;

    int lrow   = tid >> 1;            // 0..127
    int lkhalf = (tid & 1) * 8;       // 0 or 8
    int aRow = bm * 128 + lrow;
    int bRow = bn * 128 + lrow;
    bool aOk = aRow < M;
    bool bOk = bRow < Nout;
    const float* apBase = A + (size_t)aRow * K + lkhalf;
    const float* bpBase = B + (size_t)bRow * K + lkhalf;

    float acc[4][4][4];
    #pragma unroll
    for (int i = 0; i < 4; i++)
        #pragma unroll
        for (int j = 0; j < 4; j++)
            #pragma unroll
            for (int c = 0; c < 4; c++) acc[i][j][c] = 0.f;

    float a[8] = {0,0,0,0,0,0,0,0};
    float b[8] = {0,0,0,0,0,0,0,0};
    if (aOk) {
        float4 v0 = *(const float4*)apBase;
        float4 v1 = *(const float4*)(apBase + 4);
        a[0]=v0.x; a[1]=v0.y; a[2]=v0.z; a[3]=v0.w;
        a[4]=v1.x; a[5]=v1.y; a[6]=v1.z; a[7]=v1.w;
    }
    if (bOk) {
        float4 v0 = *(const float4*)bpBase;
        float4 v1 = *(const float4*)(bpBase + 4);
        b[0]=v0.x; b[1]=v0.y; b[2]=v0.z; b[3]=v0.w;
        b[4]=v1.x; b[5]=v1.y; b[6]=v1.z; b[7]=v1.w;
    }

    for (int k0 = 0; k0 < K; k0 += 16) {
        __syncthreads();
        #pragma unroll
        for (int q = 0; q < 8; q++) {
            unsigned hi, lo;
            split_tf32(a[q], hi, lo);
            AsH[(lkhalf + q) * SMS + lrow] = hi;
            AsL[(lkhalf + q) * SMS + lrow] = lo;
            split_tf32(b[q], hi, lo);
            BsH[(lkhalf + q) * SMS + lrow] = hi;
            BsL[(lkhalf + q) * SMS + lrow] = lo;
        }
        __syncthreads();

        // prefetch next tile (overlaps with mma below)
        if (k0 + 16 < K) {
            if (aOk) {
                const float* ap = apBase + k0 + 16;
                float4 v0 = *(const float4*)ap;
                float4 v1 = *(const float4*)(ap + 4);
                a[0]=v0.x; a[1]=v0.y; a[2]=v0.z; a[3]=v0.w;
                a[4]=v1.x; a[5]=v1.y; a[6]=v1.z; a[7]=v1.w;
            }
            if (bOk) {
                const float* bp = bpBase + k0 + 16;
                float4 v0 = *(const float4*)bp;
                float4 v1 = *(const float4*)(bp + 4);
                b[0]=v0.x; b[1]=v0.y; b[2]=v0.z; b[3]=v0.w;
                b[4]=v1.x; b[5]=v1.y; b[6]=v1.z; b[7]=v1.w;
            }
        }

        #pragma unroll
        for (int s = 0; s < 2; s++) {
            int k8 = s * 8;
            unsigned afH[4][4], afL[4][4];
            #pragma unroll
            for (int i = 0; i < 4; i++) {
                int mrow = mb + i * 16 + qm;
                int o0 = (k8 + qk) * SMS + mrow;
                int o1 = (k8 + qk + 4) * SMS + mrow;
                afH[i][0] = AsH[o0];     afL[i][0] = AsL[o0];
                afH[i][1] = AsH[o0 + 8]; afL[i][1] = AsL[o0 + 8];
                afH[i][2] = AsH[o1];     afL[i][2] = AsL[o1];
                afH[i][3] = AsH[o1 + 8]; afL[i][3] = AsL[o1 + 8];
            }
            unsigned bfH[4][2], bfL[4][2];
            #pragma unroll
            for (int j = 0; j < 4; j++) {
                int ncol = nb + j * 8 + qm;
                bfH[j][0] = BsH[(k8 + qk) * SMS + ncol];
                bfH[j][1] = BsH[(k8 + qk + 4) * SMS + ncol];
                bfL[j][0] = BsL[(k8 + qk) * SMS + ncol];
                bfL[j][1] = BsL[(k8 + qk + 4) * SMS + ncol];
            }
            #pragma unroll
            for (int i = 0; i < 4; i++)
                #pragma unroll
                for (int j = 0; j < 4; j++) {
                    mma_tf32(acc[i][j], afL[i], bfH[j]);   // lo*hi
                    mma_tf32(acc[i][j], afH[i], bfL[j]);   // hi*lo
                    mma_tf32(acc[i][j], afH[i], bfH[j]);   // hi*hi
                }
        }
    }

    #pragma unroll
    for (int i = 0; i < 4; i++) {
        int r0 = bm * 128 + mb + i * 16 + qm;
        int r1 = r0 + 8;
        #pragma unroll
        for (int j = 0; j < 4; j++) {
            int col = bn * 128 + nb + j * 8 + (lane & 3) * 2;
            if (r0 < M)
                *(float2*)(C + (size_t)r0 * Nout + col) = make_float2(acc[i][j][0], acc[i][j][1]);
            if (r1 < M)
                *(float2*)(C + (size_t)r1 * Nout + col) = make_float2(acc[i][j][2], acc[i][j][3]);
        }
    }
}

// ---------------- fused GRU elementwise ----------------
__global__ void gru_kernel(const float* __restrict__ hv,
                           const float* __restrict__ b_ih, const float* __restrict__ b_hh,
                           const float* __restrict__ u1, const float* __restrict__ u2,
                           float* __restrict__ out, int N)
{
    int idx = blockIdx.x * blockDim.x + threadIdx.x;
    if (idx >= N * H) return;
    int n = idx >> 7, c = idx & 127;
    float d = g_deg[n], s = g_se[n];
    size_t b = (size_t)n * H3;

    float ir = g_gi[b + c]         + s * u1[c]         + d * u2[c]         + b_ih[c];
    float iz = g_gi[b + H + c]     + s * u1[H + c]     + d * u2[H + c]     + b_ih[H + c];
    float in_ = g_gi[b + 2*H + c]  + s * u1[2*H + c]   + d * u2[2*H + c]   + b_ih[2*H + c];
    float hr = g_gh[b + c]         + b_hh[c];
    float hz = g_gh[b + H + c]     + b_hh[H + c];
    float hn = g_gh[b + 2*H + c]   + b_hh[2*H + c];

    float r = 1.f / (1.f + expf(-(ir + hr)));
    float z = 1.f / (1.f + expf(-(iz + hz)));
    float nn = tanhf(in_ + r * hn);
    float h  = hv[(size_t)n * H + c];
    out[(size_t)n * H + c] = (1.f - z) * nn + z * h;
}

// ---------------- launch ----------------
extern "C" void kernel_launch(void* const* d_in, const int* in_sizes, int n_in,
                              void* d_out, int out_size)
{
    const float* hv0   = (const float*)d_in[0];
    const float* he    = (const float*)d_in[1];
    const int*   src   = (const int*)d_in[2];
    const int*   dst   = (const int*)d_in[3];
    const float* W_msg = (const float*)d_in[4];
    const float* b_msg = (const float*)d_in[5];
    const float* W_ih  = (const float*)d_in[6];
    const float* W_hh  = (const float*)d_in[7];
    const float* b_ih  = (const float*)d_in[8];
    const float* b_hh  = (const float*)d_in[9];

    int N = in_sizes[0] / H;
    int E = in_sizes[2];
    int T = in_sizes[8] / H3;
    if (T > MAXT) T = MAXT;

    float *pX, *pgi, *pgh, *ph0, *ph1, *pdeg, *pse, *pWc, *pu1, *pu2;
    cudaGetSymbolAddress((void**)&pX,  g_X);
    cudaGetSymbolAddress((void**)&pgi, g_gi);
    cudaGetSymbolAddress((void**)&pgh, g_gh);
    cudaGetSymbolAddress((void**)&ph0, g_h0);
    cudaGetSymbolAddress((void**)&ph1, g_h1);
    cudaGetSymbolAddress((void**)&pdeg, g_deg);
    cudaGetSymbolAddress((void**)&pse,  g_se);
    cudaGetSymbolAddress((void**)&pWc,  g_Wc);
    cudaGetSymbolAddress((void**)&pu1,  g_u1);
    cudaGetSymbolAddress((void**)&pu2,  g_u2);

    // aggregates + CSR build (once per launch)
    zero_kernel<<<256, 256>>>(pdeg, (size_t)N);
    zero_kernel<<<256, 256>>>(pse,  (size_t)N);
    degse_kernel<<<(E + 255) / 256, 256>>>(dst, he, E);
    scan_kernel<<<1, 1024>>>(N);
    fill_kernel<<<(E + 255) / 256, 256>>>(src, dst, E);

    // weight folds
    long wc_total = (long)T * H3 * H2;
    fold_wc_kernel<<<(int)((wc_total + 255) / 256), 256>>>(W_ih, W_msg, T);
    fold_u_kernel<<<(T * H3 + 255) / 256, 256>>>(W_ih, W_msg, b_msg, T);

    const float* cur = hv0;
    for (int t = 0; t < T; t++) {
        gatherx_kernel<<<(N * 32 + 255) / 256, 256>>>(cur, N);

        dim3 g1((N + 127) / 128, H3 / 128);
        mma_tf32x3_nt<<<g1, 256>>>(pX, pWc + (size_t)t * H3 * H2, pgi, N, H3, H2);
        mma_tf32x3_nt<<<g1, 256>>>(cur, W_hh + (size_t)t * H3 * H, pgh, N, H3, H);

        float* outp = (t == T - 1) ? (float*)d_out : ((t & 1) ? ph1 : ph0);
        gru_kernel<<<(N * H + 255) / 256, 256>>>(cur, b_ih + (size_t)t * H3, b_hh + (size_t)t * H3,
                                                 pu1 + (size_t)t * H3, pu2 + (size_t)t * H3,
                                                 outp, N);
        cur = outp;
    }
}

// round 6
// speedup vs baseline: 1.3732x; 1.3732x over previous
#include <cuda_runtime.h>
#include <cuda_fp16.h>
#include <math.h>
#include <stdint.h>

#define H   128
#define H2  256
#define H3  384
#define WMC 257          // W_msg columns = 2H+1

#define MAXN 50000
#define MAXE 800000
#define MAXT 4

// ---------------- scratch (static device globals; no allocation) ----------------
__device__ float g_X  [(size_t)MAXN * H2];   // [deg*hv, S]
__device__ float g_gi [(size_t)MAXN * H3];
__device__ float g_gh [(size_t)MAXN * H3];
__device__ float g_h0 [(size_t)MAXN * H];
__device__ float g_h1 [(size_t)MAXN * H];
__device__ float g_deg[MAXN];
__device__ float g_se [MAXN];
__device__ float g_Wc [(size_t)MAXT * H3 * H2];  // W_ih @ W_msg[:, :2H]
__device__ float g_u1 [MAXT * H3];               // W_ih @ w_e
__device__ float g_u2 [MAXT * H3];               // W_ih @ b_msg
__device__ int   g_off [MAXN + 1];               // CSR offsets (by dst)
__device__ int   g_cur [MAXN];                   // fill cursors
__device__ int   g_csrc[MAXE];                   // CSR src lists

// ---------------- utility ----------------
__global__ void zero_kernel(float* __restrict__ p, size_t n) {
    size_t i = (size_t)blockIdx.x * blockDim.x + threadIdx.x;
    size_t stride = (size_t)gridDim.x * blockDim.x;
    for (; i < n; i += stride) p[i] = 0.f;
}

__global__ void degse_kernel(const int* __restrict__ dst, const float* __restrict__ he, int E) {
    int e = blockIdx.x * blockDim.x + threadIdx.x;
    if (e >= E) return;
    int d = dst[e];
    atomicAdd(&g_deg[d], 1.0f);
    atomicAdd(&g_se[d], he[e]);
}

// ---------------- CSR prefix scan: warp-shuffle version ----------------
__global__ void scan_kernel(int N) {
    __shared__ int wsum[32];
    __shared__ int carry;
    int tid = threadIdx.x, lane = tid & 31, wid = tid >> 5;
    if (tid == 0) carry = 0;
    __syncthreads();
    for (int base = 0; base < N; base += 1024) {
        int i = base + tid;
        int v = (i < N) ? (int)g_deg[i] : 0;
        int x = v;
        #pragma unroll
        for (int o = 1; o < 32; o <<= 1) {
            int t = __shfl_up_sync(0xFFFFFFFFu, x, o);
            if (lane >= o) x += t;
        }
        if (lane == 31) wsum[wid] = x;
        __syncthreads();
        if (wid == 0) {
            int s = wsum[lane];
            #pragma unroll
            for (int o = 1; o < 32; o <<= 1) {
                int t = __shfl_up_sync(0xFFFFFFFFu, s, o);
                if (lane >= o) s += t;
            }
            wsum[lane] = s;
        }
        __syncthreads();
        int wpre = (wid == 0) ? 0 : wsum[wid - 1];
        if (i < N) {
            int ex = carry + wpre + x - v;
            g_off[i] = ex;
            g_cur[i] = ex;
        }
        int total = wsum[31];
        __syncthreads();
        if (tid == 0) carry += total;
        __syncthreads();
    }
    if (threadIdx.x == 0) g_off[N] = carry;
}

__global__ void fill_kernel(const int* __restrict__ src, const int* __restrict__ dst, int E) {
    int e = blockIdx.x * blockDim.x + threadIdx.x;
    if (e >= E) return;
    int pos = atomicAdd(&g_cur[dst[e]], 1);
    g_csrc[pos] = src[e];
}

// ---------------- weight folding ----------------
__global__ void fold_wc_kernel(const float* __restrict__ W_ih, const float* __restrict__ W_msg, int T) {
    long idx = (long)blockIdx.x * blockDim.x + threadIdx.x;
    if (idx >= (long)T * H3 * H2) return;
    int k = (int)(idx % H2);
    int j = (int)((idx / H2) % H3);
    int t = (int)(idx / ((long)H2 * H3));
    const float* wi = W_ih + ((size_t)t * H3 + j) * H2;
    const float* wm = W_msg + (size_t)t * H2 * WMC + k;
    float a0 = 0.f, a1 = 0.f, a2 = 0.f, a3 = 0.f;
    #pragma unroll 2
    for (int i = 0; i < H2; i += 4) {
        a0 += __ldg(wi + i)     * __ldg(wm + (size_t)(i)     * WMC);
        a1 += __ldg(wi + i + 1) * __ldg(wm + (size_t)(i + 1) * WMC);
        a2 += __ldg(wi + i + 2) * __ldg(wm + (size_t)(i + 2) * WMC);
        a3 += __ldg(wi + i + 3) * __ldg(wm + (size_t)(i + 3) * WMC);
    }
    g_Wc[idx] = (a0 + a1) + (a2 + a3);
}

__global__ void fold_u_kernel(const float* __restrict__ W_ih, const float* __restrict__ W_msg,
                              const float* __restrict__ b_msg, int T) {
    int idx = blockIdx.x * blockDim.x + threadIdx.x;
    if (idx >= T * H3) return;
    int j = idx % H3, t = idx / H3;
    const float* wi = W_ih + ((size_t)t * H3 + j) * H2;
    const float* wm = W_msg + (size_t)t * H2 * WMC;
    const float* bm = b_msg + (size_t)t * H2;
    float a1 = 0.f, a2 = 0.f;
    for (int i = 0; i < H2; i++) {
        float w = wi[i];
        a1 += w * wm[(size_t)i * WMC + H2];
        a2 += w * bm[i];
    }
    g_u1[idx] = a1;
    g_u2[idx] = a2;
}

// ---------------- gather + X build: one warp per node ----------------
__global__ void gatherx_kernel(const float* __restrict__ hv, int N) {
    int n = (blockIdx.x * blockDim.x + threadIdx.x) >> 5;
    int lane = threadIdx.x & 31;
    if (n >= N) return;
    int beg = g_off[n], end = g_off[n + 1];
    float4 acc = make_float4(0.f, 0.f, 0.f, 0.f);
    for (int e = beg; e < end; e++) {
        int s = __ldg(g_csrc + e);
        float4 v = *(((const float4*)(hv + (size_t)s * H)) + lane);
        acc.x += v.x; acc.y += v.y; acc.z += v.z; acc.w += v.w;
    }
    float dg = (float)(end - beg);
    float4 hvv = *(((const float4*)(hv + (size_t)n * H)) + lane);
    hvv.x *= dg; hvv.y *= dg; hvv.z *= dg; hvv.w *= dg;
    float4* xp = (float4*)(g_X + (size_t)n * H2);
    xp[lane] = hvv;
    xp[lane + 32] = acc;
}

// ---------------- 3xFP16 tensor-core GEMM (NT): C = A @ B^T, fp32-accurate ---------
// 128x128 block tile, BK=16, 256 threads (8 warps, 2x4), warp tile 64x32.
// Operands split fp16 hi/lo, 3x mma.sync.m16n8k16: lo*hi + hi*lo + hi*hi.
// Smem: half2 packed along k (8 k2-slots), stride 136; 2-stage double buffer,
// ONE __syncthreads per K-chunk.
#define SMS 136

__device__ __forceinline__ void split_h2(float x, float y, uint32_t& hi, uint32_t& lo) {
    __half hx = __float2half_rn(x);
    __half hy = __float2half_rn(y);
    __half lx = __float2half_rn(x - __half2float(hx));
    __half ly = __float2half_rn(y - __half2float(hy));
    __half2 h = __halves2half2(hx, hy);
    __half2 l = __halves2half2(lx, ly);
    hi = *(uint32_t*)&h;
    lo = *(uint32_t*)&l;
}

__device__ __forceinline__ void mma_f16(float* acc, const uint32_t* a, const uint32_t* b) {
    asm volatile(
        "mma.sync.aligned.m16n8k16.row.col.f32.f16.f16.f32 "
        "{%0,%1,%2,%3}, {%4,%5,%6,%7}, {%8,%9}, {%0,%1,%2,%3};"
        : "+f"(acc[0]), "+f"(acc[1]), "+f"(acc[2]), "+f"(acc[3])
        : "r"(a[0]), "r"(a[1]), "r"(a[2]), "r"(a[3]), "r"(b[0]), "r"(b[1]));
}

__global__ __launch_bounds__(256) void mma_f16x3_nt(
    const float* __restrict__ A, const float* __restrict__ B, float* __restrict__ C,
    int M, int Nout, int K)
{
    // [stage][k2-slot][row], half2 payload
    __shared__ uint32_t AsH[2][8 * SMS];
    __shared__ uint32_t AsL[2][8 * SMS];
    __shared__ uint32_t BsH[2][8 * SMS];
    __shared__ uint32_t BsL[2][8 * SMS];

    int bm = blockIdx.x, bn = blockIdx.y;
    int tid = threadIdx.x;
    int lane = tid & 31;
    int warp = tid >> 5;
    int wm = warp >> 2;        // 0..1
    int wn = warp & 3;         // 0..3
    int mb = wm * 64;
    int nb = wn * 32;
    int qk = lane & 3;
    int qm = lane >> 2;

    int lrow = tid >> 1;              // 0..127
    int lk2  = (tid & 1) * 4;         // half2 slot base: 0 or 4 (k offset 0 or 8)
    int aRow = bm * 128 + lrow;
    int bRow = bn * 128 + lrow;
    bool aOk = aRow < M;
    bool bOk = bRow < Nout;
    const float* apBase = A + (size_t)aRow * K + lk2 * 2;
    const float* bpBase = B + (size_t)bRow * K + lk2 * 2;

    float acc[4][4][4];
    #pragma unroll
    for (int i = 0; i < 4; i++)
        #pragma unroll
        for (int j = 0; j < 4; j++)
            #pragma unroll
            for (int c = 0; c < 4; c++) acc[i][j][c] = 0.f;

    float a[8] = {0,0,0,0,0,0,0,0};
    float b[8] = {0,0,0,0,0,0,0,0};
    if (aOk) {
        float4 v0 = *(const float4*)apBase;
        float4 v1 = *(const float4*)(apBase + 4);
        a[0]=v0.x; a[1]=v0.y; a[2]=v0.z; a[3]=v0.w;
        a[4]=v1.x; a[5]=v1.y; a[6]=v1.z; a[7]=v1.w;
    }
    if (bOk) {
        float4 v0 = *(const float4*)bpBase;
        float4 v1 = *(const float4*)(bpBase + 4);
        b[0]=v0.x; b[1]=v0.y; b[2]=v0.z; b[3]=v0.w;
        b[4]=v1.x; b[5]=v1.y; b[6]=v1.z; b[7]=v1.w;
    }
    // store chunk 0 into stage 0
    #pragma unroll
    for (int q = 0; q < 4; q++) {
        uint32_t hi, lo;
        split_h2(a[2*q], a[2*q+1], hi, lo);
        AsH[0][(lk2 + q) * SMS + lrow] = hi;
        AsL[0][(lk2 + q) * SMS + lrow] = lo;
        split_h2(b[2*q], b[2*q+1], hi, lo);
        BsH[0][(lk2 + q) * SMS + lrow] = hi;
        BsL[0][(lk2 + q) * SMS + lrow] = lo;
    }

    int nChunks = K >> 4;
    for (int c = 0; c < nChunks; c++) {
        int cur = c & 1;
        __syncthreads();   // stage[cur] stores visible; all warps past iter c-1

        // prefetch next chunk into regs (overlaps the mma below)
        if (c + 1 < nChunks) {
            if (aOk) {
                const float* ap = apBase + (c + 1) * 16;
                float4 v0 = *(const float4*)ap;
                float4 v1 = *(const float4*)(ap + 4);
                a[0]=v0.x; a[1]=v0.y; a[2]=v0.z; a[3]=v0.w;
                a[4]=v1.x; a[5]=v1.y; a[6]=v1.z; a[7]=v1.w;
            }
            if (bOk) {
                const float* bp = bpBase + (c + 1) * 16;
                float4 v0 = *(const float4*)bp;
                float4 v1 = *(const float4*)(bp + 4);
                b[0]=v0.x; b[1]=v0.y; b[2]=v0.z; b[3]=v0.w;
                b[4]=v1.x; b[5]=v1.y; b[6]=v1.z; b[7]=v1.w;
            }
        }

        // fragments + mma (k16 in one instruction)
        uint32_t afH[4][4], afL[4][4];
        #pragma unroll
        for (int i = 0; i < 4; i++) {
            int mrow = mb + i * 16 + qm;
            int o0 = qk * SMS + mrow;
            int o1 = (qk + 4) * SMS + mrow;
            afH[i][0] = AsH[cur][o0];     afL[i][0] = AsL[cur][o0];
            afH[i][1] = AsH[cur][o0 + 8]; afL[i][1] = AsL[cur][o0 + 8];
            afH[i][2] = AsH[cur][o1];     afL[i][2] = AsL[cur][o1];
            afH[i][3] = AsH[cur][o1 + 8]; afL[i][3] = AsL[cur][o1 + 8];
        }
        uint32_t bfH[4][2], bfL[4][2];
        #pragma unroll
        for (int j = 0; j < 4; j++) {
            int ncol = nb + j * 8 + qm;
            bfH[j][0] = BsH[cur][qk * SMS + ncol];
            bfH[j][1] = BsH[cur][(qk + 4) * SMS + ncol];
            bfL[j][0] = BsL[cur][qk * SMS + ncol];
            bfL[j][1] = BsL[cur][(qk + 4) * SMS + ncol];
        }
        #pragma unroll
        for (int i = 0; i < 4; i++)
            #pragma unroll
            for (int j = 0; j < 4; j++) {
                mma_f16(acc[i][j], afL[i], bfH[j]);   // lo*hi
                mma_f16(acc[i][j], afH[i], bfL[j]);   // hi*lo
                mma_f16(acc[i][j], afH[i], bfH[j]);   // hi*hi
            }

        // store next chunk into the other stage (read last in iter c-1 -> free)
        if (c + 1 < nChunks) {
            int nxt = cur ^ 1;
            #pragma unroll
            for (int q = 0; q < 4; q++) {
                uint32_t hi, lo;
                split_h2(a[2*q], a[2*q+1], hi, lo);
                AsH[nxt][(lk2 + q) * SMS + lrow] = hi;
                AsL[nxt][(lk2 + q) * SMS + lrow] = lo;
                split_h2(b[2*q], b[2*q+1], hi, lo);
                BsH[nxt][(lk2 + q) * SMS + lrow] = hi;
                BsL[nxt][(lk2 + q) * SMS + lrow] = lo;
            }
        }
    }

    #pragma unroll
    for (int i = 0; i < 4; i++) {
        int r0 = bm * 128 + mb + i * 16 + qm;
        int r1 = r0 + 8;
        #pragma unroll
        for (int j = 0; j < 4; j++) {
            int col = bn * 128 + nb + j * 8 + (lane & 3) * 2;
            if (r0 < M)
                *(float2*)(C + (size_t)r0 * Nout + col) = make_float2(acc[i][j][0], acc[i][j][1]);
            if (r1 < M)
                *(float2*)(C + (size_t)r1 * Nout + col) = make_float2(acc[i][j][2], acc[i][j][3]);
        }
    }
}

// ---------------- fused GRU elementwise ----------------
__global__ void gru_kernel(const float* __restrict__ hv,
                           const float* __restrict__ b_ih, const float* __restrict__ b_hh,
                           const float* __restrict__ u1, const float* __restrict__ u2,
                           float* __restrict__ out, int N)
{
    int idx = blockIdx.x * blockDim.x + threadIdx.x;
    if (idx >= N * H) return;
    int n = idx >> 7, c = idx & 127;
    float d = g_deg[n], s = g_se[n];
    size_t b = (size_t)n * H3;

    float ir = g_gi[b + c]         + s * u1[c]         + d * u2[c]         + b_ih[c];
    float iz = g_gi[b + H + c]     + s * u1[H + c]     + d * u2[H + c]     + b_ih[H + c];
    float in_ = g_gi[b + 2*H + c]  + s * u1[2*H + c]   + d * u2[2*H + c]   + b_ih[2*H + c];
    float hr = g_gh[b + c]         + b_hh[c];
    float hz = g_gh[b + H + c]     + b_hh[H + c];
    float hn = g_gh[b + 2*H + c]   + b_hh[2*H + c];

    float r = 1.f / (1.f + expf(-(ir + hr)));
    float z = 1.f / (1.f + expf(-(iz + hz)));
    float nn = tanhf(in_ + r * hn);
    float h  = hv[(size_t)n * H + c];
    out[(size_t)n * H + c] = (1.f - z) * nn + z * h;
}

// ---------------- launch ----------------
extern "C" void kernel_launch(void* const* d_in, const int* in_sizes, int n_in,
                              void* d_out, int out_size)
{
    const float* hv0   = (const float*)d_in[0];
    const float* he    = (const float*)d_in[1];
    const int*   src   = (const int*)d_in[2];
    const int*   dst   = (const int*)d_in[3];
    const float* W_msg = (const float*)d_in[4];
    const float* b_msg = (const float*)d_in[5];
    const float* W_ih  = (const float*)d_in[6];
    const float* W_hh  = (const float*)d_in[7];
    const float* b_ih  = (const float*)d_in[8];
    const float* b_hh  = (const float*)d_in[9];

    int N = in_sizes[0] / H;
    int E = in_sizes[2];
    int T = in_sizes[8] / H3;
    if (T > MAXT) T = MAXT;

    float *pX, *pgi, *pgh, *ph0, *ph1, *pdeg, *pse, *pWc, *pu1, *pu2;
    cudaGetSymbolAddress((void**)&pX,  g_X);
    cudaGetSymbolAddress((void**)&pgi, g_gi);
    cudaGetSymbolAddress((void**)&pgh, g_gh);
    cudaGetSymbolAddress((void**)&ph0, g_h0);
    cudaGetSymbolAddress((void**)&ph1, g_h1);
    cudaGetSymbolAddress((void**)&pdeg, g_deg);
    cudaGetSymbolAddress((void**)&pse,  g_se);
    cudaGetSymbolAddress((void**)&pWc,  g_Wc);
    cudaGetSymbolAddress((void**)&pu1,  g_u1);
    cudaGetSymbolAddress((void**)&pu2,  g_u2);

    // aggregates + CSR build (once per launch)
    zero_kernel<<<256, 256>>>(pdeg, (size_t)N);
    zero_kernel<<<256, 256>>>(pse,  (size_t)N);
    degse_kernel<<<(E + 255) / 256, 256>>>(dst, he, E);
    scan_kernel<<<1, 1024>>>(N);
    fill_kernel<<<(E + 255) / 256, 256>>>(src, dst, E);

    // weight folds
    long wc_total = (long)T * H3 * H2;
    fold_wc_kernel<<<(int)((wc_total + 255) / 256), 256>>>(W_ih, W_msg, T);
    fold_u_kernel<<<(T * H3 + 255) / 256, 256>>>(W_ih, W_msg, b_msg, T);

    const float* cur = hv0;
    for (int t = 0; t < T; t++) {
        gatherx_kernel<<<(N * 32 + 255) / 256, 256>>>(cur, N);

        dim3 g1((N + 127) / 128, H3 / 128);
        mma_f16x3_nt<<<g1, 256>>>(pX, pWc + (size_t)t * H3 * H2, pgi, N, H3, H2);
        mma_f16x3_nt<<<g1, 256>>>(cur, W_hh + (size_t)t * H3 * H, pgh, N, H3, H);

        float* outp = (t == T - 1) ? (float*)d_out : ((t & 1) ? ph1 : ph0);
        gru_kernel<<<(N * H + 255) / 256, 256>>>(cur, b_ih + (size_t)t * H3, b_hh + (size_t)t * H3,
                                                 pu1 + (size_t)t * H3, pu2 + (size_t)t * H3,
                                                 outp, N);
        cur = outp;
    }
}

// round 7
// speedup vs baseline: 1.5599x; 1.1360x over previous
#include <cuda_runtime.h>
#include <cuda_fp16.h>
#include <math.h>
#include <stdint.h>

#define H   128
#define H2  256
#define H3  384
#define WMC 257          // W_msg columns = 2H+1

#define MAXN 50000
#define MAXE 800000
#define MAXT 4
#define MAXNB ((MAXN + 1023) / 1024)

// ---------------- scratch (static device globals; no allocation) ----------------
__device__ float g_X  [(size_t)MAXN * H2];   // [deg*hv, S]
__device__ float g_gi [(size_t)MAXN * H3];
__device__ float g_gh [(size_t)MAXN * H3];
__device__ float g_h0 [(size_t)MAXN * H];
__device__ float g_h1 [(size_t)MAXN * H];
__device__ float g_deg[MAXN];
__device__ float g_se [MAXN];
__device__ float g_Wc [(size_t)MAXT * H3 * H2];  // W_ih @ W_msg[:, :2H]
__device__ float g_u1 [MAXT * H3];               // W_ih @ w_e
__device__ float g_u2 [MAXT * H3];               // W_ih @ b_msg
__device__ int   g_off [MAXN + 1];               // CSR offsets (by dst)
__device__ int   g_cur [MAXN];                   // fill cursors
__device__ int   g_csrc[MAXE];                   // CSR src lists
__device__ int   g_bsum[MAXNB];                  // scan partials
__device__ int   g_bpre[MAXNB];

// ---------------- utility ----------------
__global__ void zero2_kernel(float* __restrict__ p, float* __restrict__ q, int n) {
    int i = blockIdx.x * blockDim.x + threadIdx.x;
    int stride = gridDim.x * blockDim.x;
    for (int k = i; k < n; k += stride) { p[k] = 0.f; q[k] = 0.f; }
}

__global__ void degse_kernel(const int* __restrict__ dst, const float* __restrict__ he, int E) {
    int e = blockIdx.x * blockDim.x + threadIdx.x;
    if (e >= E) return;
    int d = dst[e];
    atomicAdd(&g_deg[d], 1.0f);
    atomicAdd(&g_se[d], he[e]);
}

// ---------------- CSR prefix scan: multi-block ----------------
__global__ void scan1_kernel(int N) {
    __shared__ int wsum[32];
    int i = blockIdx.x * 1024 + threadIdx.x;
    int lane = threadIdx.x & 31, wid = threadIdx.x >> 5;
    int v = (i < N) ? (int)g_deg[i] : 0;
    int x = v;
    #pragma unroll
    for (int o = 1; o < 32; o <<= 1) {
        int t = __shfl_up_sync(0xFFFFFFFFu, x, o);
        if (lane >= o) x += t;
    }
    if (lane == 31) wsum[wid] = x;
    __syncthreads();
    if (wid == 0) {
        int s = wsum[lane];
        #pragma unroll
        for (int o = 1; o < 32; o <<= 1) {
            int t = __shfl_up_sync(0xFFFFFFFFu, s, o);
            if (lane >= o) s += t;
        }
        wsum[lane] = s;
    }
    __syncthreads();
    int wpre = (wid == 0) ? 0 : wsum[wid - 1];
    if (i < N) g_off[i] = wpre + x - v;          // exclusive within block
    if (threadIdx.x == 1023) g_bsum[blockIdx.x] = wpre + x;
}

__global__ void scan2_kernel(int nb) {
    if (threadIdx.x == 0) {
        int s = 0;
        for (int b = 0; b < nb; b++) { int t = g_bsum[b]; g_bpre[b] = s; s += t; }
    }
}

__global__ void scan3_kernel(int N, int E) {
    int i = blockIdx.x * 1024 + threadIdx.x;
    if (i < N) {
        int o = g_off[i] + g_bpre[blockIdx.x];
        g_off[i] = o;
        g_cur[i] = o;
    }
    if (i == 0) g_off[N] = E;
}

__global__ void fill_kernel(const int* __restrict__ src, const int* __restrict__ dst, int E) {
    int e = blockIdx.x * blockDim.x + threadIdx.x;
    if (e >= E) return;
    int pos = atomicAdd(&g_cur[dst[e]], 1);
    g_csrc[pos] = src[e];
}

// ---------------- weight folding ----------------
__global__ void fold_wc_kernel(const float* __restrict__ W_ih, const float* __restrict__ W_msg, int T) {
    long idx = (long)blockIdx.x * blockDim.x + threadIdx.x;
    if (idx >= (long)T * H3 * H2) return;
    int k = (int)(idx % H2);
    int j = (int)((idx / H2) % H3);
    int t = (int)(idx / ((long)H2 * H3));
    const float* wi = W_ih + ((size_t)t * H3 + j) * H2;
    const float* wm = W_msg + (size_t)t * H2 * WMC + k;
    float a0 = 0.f, a1 = 0.f, a2 = 0.f, a3 = 0.f;
    #pragma unroll 2
    for (int i = 0; i < H2; i += 4) {
        a0 += __ldg(wi + i)     * __ldg(wm + (size_t)(i)     * WMC);
        a1 += __ldg(wi + i + 1) * __ldg(wm + (size_t)(i + 1) * WMC);
        a2 += __ldg(wi + i + 2) * __ldg(wm + (size_t)(i + 2) * WMC);
        a3 += __ldg(wi + i + 3) * __ldg(wm + (size_t)(i + 3) * WMC);
    }
    g_Wc[idx] = (a0 + a1) + (a2 + a3);
}

__global__ void fold_u_kernel(const float* __restrict__ W_ih, const float* __restrict__ W_msg,
                              const float* __restrict__ b_msg, int T) {
    int idx = blockIdx.x * blockDim.x + threadIdx.x;
    if (idx >= T * H3) return;
    int j = idx % H3, t = idx / H3;
    const float* wi = W_ih + ((size_t)t * H3 + j) * H2;
    const float* wm = W_msg + (size_t)t * H2 * WMC;
    const float* bm = b_msg + (size_t)t * H2;
    float a1 = 0.f, a2 = 0.f;
    for (int i = 0; i < H2; i++) {
        float w = wi[i];
        a1 += w * wm[(size_t)i * WMC + H2];
        a2 += w * bm[i];
    }
    g_u1[idx] = a1;
    g_u2[idx] = a2;
}

// ---------------- gather + X build: one warp per node, unroll-2 ----------------
__global__ void gatherx_kernel(const float* __restrict__ hv, int N) {
    int n = (blockIdx.x * blockDim.x + threadIdx.x) >> 5;
    int lane = threadIdx.x & 31;
    if (n >= N) return;
    int beg = g_off[n], end = g_off[n + 1];
    float4 acc0 = make_float4(0.f, 0.f, 0.f, 0.f);
    float4 acc1 = make_float4(0.f, 0.f, 0.f, 0.f);
    int e = beg;
    for (; e + 2 <= end; e += 2) {
        int s0 = __ldg(g_csrc + e);
        int s1 = __ldg(g_csrc + e + 1);
        float4 v0 = *(((const float4*)(hv + (size_t)s0 * H)) + lane);
        float4 v1 = *(((const float4*)(hv + (size_t)s1 * H)) + lane);
        acc0.x += v0.x; acc0.y += v0.y; acc0.z += v0.z; acc0.w += v0.w;
        acc1.x += v1.x; acc1.y += v1.y; acc1.z += v1.z; acc1.w += v1.w;
    }
    if (e < end) {
        int s0 = __ldg(g_csrc + e);
        float4 v0 = *(((const float4*)(hv + (size_t)s0 * H)) + lane);
        acc0.x += v0.x; acc0.y += v0.y; acc0.z += v0.z; acc0.w += v0.w;
    }
    acc0.x += acc1.x; acc0.y += acc1.y; acc0.z += acc1.z; acc0.w += acc1.w;
    float dg = (float)(end - beg);
    float4 hvv = *(((const float4*)(hv + (size_t)n * H)) + lane);
    hvv.x *= dg; hvv.y *= dg; hvv.z *= dg; hvv.w *= dg;
    float4* xp = (float4*)(g_X + (size_t)n * H2);
    xp[lane] = hvv;
    xp[lane + 32] = acc0;
}

// ---------------- 3xFP16 tensor-core GEMM (NT): C = A @ B^T, fp32-accurate ---------
#define SMS 136

__device__ __forceinline__ void split_h2(float x, float y, uint32_t& hi, uint32_t& lo) {
    __half hx = __float2half_rn(x);
    __half hy = __float2half_rn(y);
    __half lx = __float2half_rn(x - __half2float(hx));
    __half ly = __float2half_rn(y - __half2float(hy));
    __half2 h = __halves2half2(hx, hy);
    __half2 l = __halves2half2(lx, ly);
    hi = *(uint32_t*)&h;
    lo = *(uint32_t*)&l;
}

__device__ __forceinline__ void mma_f16(float* acc, const uint32_t* a, const uint32_t* b) {
    asm volatile(
        "mma.sync.aligned.m16n8k16.row.col.f32.f16.f16.f32 "
        "{%0,%1,%2,%3}, {%4,%5,%6,%7}, {%8,%9}, {%0,%1,%2,%3};"
        : "+f"(acc[0]), "+f"(acc[1]), "+f"(acc[2]), "+f"(acc[3])
        : "r"(a[0]), "r"(a[1]), "r"(a[2]), "r"(a[3]), "r"(b[0]), "r"(b[1]));
}

__global__ __launch_bounds__(256) void mma_f16x3_nt(
    const float* __restrict__ A, const float* __restrict__ B, float* __restrict__ C,
    int M, int Nout, int K)
{
    __shared__ uint32_t AsH[2][8 * SMS];
    __shared__ uint32_t AsL[2][8 * SMS];
    __shared__ uint32_t BsH[2][8 * SMS];
    __shared__ uint32_t BsL[2][8 * SMS];

    int bm = blockIdx.x, bn = blockIdx.y;
    int tid = threadIdx.x;
    int lane = tid & 31;
    int warp = tid >> 5;
    int wm = warp >> 2;
    int wn = warp & 3;
    int mb = wm * 64;
    int nb = wn * 32;
    int qk = lane & 3;
    int qm = lane >> 2;

    int lrow = tid >> 1;
    int lk2  = (tid & 1) * 4;
    int aRow = bm * 128 + lrow;
    int bRow = bn * 128 + lrow;
    bool aOk = aRow < M;
    bool bOk = bRow < Nout;
    const float* apBase = A + (size_t)aRow * K + lk2 * 2;
    const float* bpBase = B + (size_t)bRow * K + lk2 * 2;

    float acc[4][4][4];
    #pragma unroll
    for (int i = 0; i < 4; i++)
        #pragma unroll
        for (int j = 0; j < 4; j++)
            #pragma unroll
            for (int c = 0; c < 4; c++) acc[i][j][c] = 0.f;

    float a[8] = {0,0,0,0,0,0,0,0};
    float b[8] = {0,0,0,0,0,0,0,0};
    if (aOk) {
        float4 v0 = *(const float4*)apBase;
        float4 v1 = *(const float4*)(apBase + 4);
        a[0]=v0.x; a[1]=v0.y; a[2]=v0.z; a[3]=v0.w;
        a[4]=v1.x; a[5]=v1.y; a[6]=v1.z; a[7]=v1.w;
    }
    if (bOk) {
        float4 v0 = *(const float4*)bpBase;
        float4 v1 = *(const float4*)(bpBase + 4);
        b[0]=v0.x; b[1]=v0.y; b[2]=v0.z; b[3]=v0.w;
        b[4]=v1.x; b[5]=v1.y; b[6]=v1.z; b[7]=v1.w;
    }
    #pragma unroll
    for (int q = 0; q < 4; q++) {
        uint32_t hi, lo;
        split_h2(a[2*q], a[2*q+1], hi, lo);
        AsH[0][(lk2 + q) * SMS + lrow] = hi;
        AsL[0][(lk2 + q) * SMS + lrow] = lo;
        split_h2(b[2*q], b[2*q+1], hi, lo);
        BsH[0][(lk2 + q) * SMS + lrow] = hi;
        BsL[0][(lk2 + q) * SMS + lrow] = lo;
    }

    int nChunks = K >> 4;
    for (int c = 0; c < nChunks; c++) {
        int cur = c & 1;
        __syncthreads();

        if (c + 1 < nChunks) {
            if (aOk) {
                const float* ap = apBase + (c + 1) * 16;
                float4 v0 = *(const float4*)ap;
                float4 v1 = *(const float4*)(ap + 4);
                a[0]=v0.x; a[1]=v0.y; a[2]=v0.z; a[3]=v0.w;
                a[4]=v1.x; a[5]=v1.y; a[6]=v1.z; a[7]=v1.w;
            }
            if (bOk) {
                const float* bp = bpBase + (c + 1) * 16;
                float4 v0 = *(const float4*)bp;
                float4 v1 = *(const float4*)(bp + 4);
                b[0]=v0.x; b[1]=v0.y; b[2]=v0.z; b[3]=v0.w;
                b[4]=v1.x; b[5]=v1.y; b[6]=v1.z; b[7]=v1.w;
            }
        }

        uint32_t afH[4][4], afL[4][4];
        #pragma unroll
        for (int i = 0; i < 4; i++) {
            int mrow = mb + i * 16 + qm;
            int o0 = qk * SMS + mrow;
            int o1 = (qk + 4) * SMS + mrow;
            afH[i][0] = AsH[cur][o0];     afL[i][0] = AsL[cur][o0];
            afH[i][1] = AsH[cur][o0 + 8]; afL[i][1] = AsL[cur][o0 + 8];
            afH[i][2] = AsH[cur][o1];     afL[i][2] = AsL[cur][o1];
            afH[i][3] = AsH[cur][o1 + 8]; afL[i][3] = AsL[cur][o1 + 8];
        }
        uint32_t bfH[4][2], bfL[4][2];
        #pragma unroll
        for (int j = 0; j < 4; j++) {
            int ncol = nb + j * 8 + qm;
            bfH[j][0] = BsH[cur][qk * SMS + ncol];
            bfH[j][1] = BsH[cur][(qk + 4) * SMS + ncol];
            bfL[j][0] = BsL[cur][qk * SMS + ncol];
            bfL[j][1] = BsL[cur][(qk + 4) * SMS + ncol];
        }
        #pragma unroll
        for (int i = 0; i < 4; i++)
            #pragma unroll
            for (int j = 0; j < 4; j++) {
                mma_f16(acc[i][j], afL[i], bfH[j]);
                mma_f16(acc[i][j], afH[i], bfL[j]);
                mma_f16(acc[i][j], afH[i], bfH[j]);
            }

        if (c + 1 < nChunks) {
            int nxt = cur ^ 1;
            #pragma unroll
            for (int q = 0; q < 4; q++) {
                uint32_t hi, lo;
                split_h2(a[2*q], a[2*q+1], hi, lo);
                AsH[nxt][(lk2 + q) * SMS + lrow] = hi;
                AsL[nxt][(lk2 + q) * SMS + lrow] = lo;
                split_h2(b[2*q], b[2*q+1], hi, lo);
                BsH[nxt][(lk2 + q) * SMS + lrow] = hi;
                BsL[nxt][(lk2 + q) * SMS + lrow] = lo;
            }
        }
    }

    #pragma unroll
    for (int i = 0; i < 4; i++) {
        int r0 = bm * 128 + mb + i * 16 + qm;
        int r1 = r0 + 8;
        #pragma unroll
        for (int j = 0; j < 4; j++) {
            int col = bn * 128 + nb + j * 8 + (lane & 3) * 2;
            if (r0 < M)
                *(float2*)(C + (size_t)r0 * Nout + col) = make_float2(acc[i][j][0], acc[i][j][1]);
            if (r1 < M)
                *(float2*)(C + (size_t)r1 * Nout + col) = make_float2(acc[i][j][2], acc[i][j][3]);
        }
    }
}

// ---------------- fused GRU elementwise ----------------
__global__ void gru_kernel(const float* __restrict__ hv,
                           const float* __restrict__ b_ih, const float* __restrict__ b_hh,
                           const float* __restrict__ u1, const float* __restrict__ u2,
                           float* __restrict__ out, int N)
{
    int idx = blockIdx.x * blockDim.x + threadIdx.x;
    if (idx >= N * H) return;
    int n = idx >> 7, c = idx & 127;
    float d = g_deg[n], s = g_se[n];
    size_t b = (size_t)n * H3;

    float ir = g_gi[b + c]         + s * u1[c]         + d * u2[c]         + b_ih[c];
    float iz = g_gi[b + H + c]     + s * u1[H + c]     + d * u2[H + c]     + b_ih[H + c];
    float in_ = g_gi[b + 2*H + c]  + s * u1[2*H + c]   + d * u2[2*H + c]   + b_ih[2*H + c];
    float hr = g_gh[b + c]         + b_hh[c];
    float hz = g_gh[b + H + c]     + b_hh[H + c];
    float hn = g_gh[b + 2*H + c]   + b_hh[2*H + c];

    float r = 1.f / (1.f + expf(-(ir + hr)));
    float z = 1.f / (1.f + expf(-(iz + hz)));
    float nn = tanhf(in_ + r * hn);
    float h  = hv[(size_t)n * H + c];
    out[(size_t)n * H + c] = (1.f - z) * nn + z * h;
}

// ---------------- launch ----------------
extern "C" void kernel_launch(void* const* d_in, const int* in_sizes, int n_in,
                              void* d_out, int out_size)
{
    const float* hv0   = (const float*)d_in[0];
    const float* he    = (const float*)d_in[1];
    const int*   src   = (const int*)d_in[2];
    const int*   dst   = (const int*)d_in[3];
    const float* W_msg = (const float*)d_in[4];
    const float* b_msg = (const float*)d_in[5];
    const float* W_ih  = (const float*)d_in[6];
    const float* W_hh  = (const float*)d_in[7];
    const float* b_ih  = (const float*)d_in[8];
    const float* b_hh  = (const float*)d_in[9];

    int N = in_sizes[0] / H;
    int E = in_sizes[2];
    int T = in_sizes[8] / H3;
    if (T > MAXT) T = MAXT;

    // one-time host resources (no device memory involved)
    static cudaStream_t s2 = nullptr;
    static cudaEvent_t evStart = nullptr, evFold = nullptr, evGh = nullptr, evGru = nullptr;
    if (!s2) {
        cudaStreamCreateWithFlags(&s2, cudaStreamNonBlocking);
        cudaEventCreateWithFlags(&evStart, cudaEventDisableTiming);
        cudaEventCreateWithFlags(&evFold,  cudaEventDisableTiming);
        cudaEventCreateWithFlags(&evGh,    cudaEventDisableTiming);
        cudaEventCreateWithFlags(&evGru,   cudaEventDisableTiming);
    }

    float *pX, *pgi, *pgh, *ph0, *ph1, *pdeg, *pse, *pWc, *pu1, *pu2;
    cudaGetSymbolAddress((void**)&pX,  g_X);
    cudaGetSymbolAddress((void**)&pgi, g_gi);
    cudaGetSymbolAddress((void**)&pgh, g_gh);
    cudaGetSymbolAddress((void**)&ph0, g_h0);
    cudaGetSymbolAddress((void**)&ph1, g_h1);
    cudaGetSymbolAddress((void**)&pdeg, g_deg);
    cudaGetSymbolAddress((void**)&pse,  g_se);
    cudaGetSymbolAddress((void**)&pWc,  g_Wc);
    cudaGetSymbolAddress((void**)&pu1,  g_u1);
    cudaGetSymbolAddress((void**)&pu2,  g_u2);

    int nb = (N + 1023) / 1024;

    // ---- fork: s2 does weight folds (+ round-0 gh GEMM), main does CSR build ----
    cudaEventRecord(evStart, 0);
    cudaStreamWaitEvent(s2, evStart, 0);

    long wc_total = (long)T * H3 * H2;
    fold_wc_kernel<<<(int)((wc_total + 255) / 256), 256, 0, s2>>>(W_ih, W_msg, T);
    fold_u_kernel<<<(T * H3 + 255) / 256, 256, 0, s2>>>(W_ih, W_msg, b_msg, T);
    cudaEventRecord(evFold, s2);

    zero2_kernel<<<128, 256>>>(pdeg, pse, N);
    degse_kernel<<<(E + 255) / 256, 256>>>(dst, he, E);
    scan1_kernel<<<nb, 1024>>>(N);
    scan2_kernel<<<1, 32>>>(nb);
    scan3_kernel<<<nb, 1024>>>(N, E);
    fill_kernel<<<(E + 255) / 256, 256>>>(src, dst, E);

    const float* cur = hv0;
    dim3 g1((N + 127) / 128, 3);
    for (int t = 0; t < T; t++) {
        // main: gather -> gi GEMM (needs Wc for all t; wait fold once)
        gatherx_kernel<<<(N * 32 + 255) / 256, 256>>>(cur, N);
        if (t == 0) cudaStreamWaitEvent(0, evFold, 0);
        mma_f16x3_nt<<<g1, 256>>>(pX, pWc + (size_t)t * H3 * H2, pgi, N, H3, H2);

        // s2: gh GEMM (independent of gather/gi; needs cur = prev gru output)
        if (t > 0) cudaStreamWaitEvent(s2, evGru, 0);
        mma_f16x3_nt<<<g1, 256, 0, s2>>>(cur, W_hh + (size_t)t * H3 * H, pgh, N, H3, H);
        cudaEventRecord(evGh, s2);

        // join, then GRU on main
        cudaStreamWaitEvent(0, evGh, 0);
        float* outp = (t == T - 1) ? (float*)d_out : ((t & 1) ? ph1 : ph0);
        gru_kernel<<<(N * H + 255) / 256, 256>>>(cur, b_ih + (size_t)t * H3, b_hh + (size_t)t * H3,
                                                 pu1 + (size_t)t * H3, pu2 + (size_t)t * H3,
                                                 outp, N);
        cudaEventRecord(evGru, 0);
        cur = outp;
    }
}